// round 10
// baseline (speedup 1.0000x reference)
#include <cuda_runtime.h>
#include <cuda_bf16.h>
#include <math.h>
#include <stdint.h>

#define N_TOK 8192
#define D 256
#define BM 64
#define BN 64
#define TPB 256
#define KSTR 264   // bf16 stride for [64][256] tiles: 528B rows, ldmatrix conflict-free
#define ESTR 72    // bf16 stride for E tile [64][64]
#define NT (N_TOK / BN)
#define TILE (BM * KSTR)   // elements per staged tile

// flash smem: Qs + 2*Ks + 3*Xs + 2*Es + red
static_assert((6 * TILE + 2 * BM * ESTR) * 2 + 512 <= 232448, "flash smem");

__device__ __align__(16) __nv_bfloat16 g_q[N_TOK * D];
__device__ __align__(16) __nv_bfloat16 g_k[N_TOK * D];
__device__ __align__(16) __nv_bfloat16 g_x[N_TOK * D];
__device__ __align__(16) __nv_bfloat16 g_attn[N_TOK * D];
__device__ float g_sq[N_TOK];
__device__ float g_feat[N_TOK];

__device__ __forceinline__ uint32_t smem_u32(const void* p) {
    return (uint32_t)__cvta_generic_to_shared(p);
}
__device__ __forceinline__ void ldmx4(uint32_t r[4], uint32_t addr) {
    asm volatile("ldmatrix.sync.aligned.m8n8.x4.shared.b16 {%0,%1,%2,%3}, [%4];"
                 : "=r"(r[0]), "=r"(r[1]), "=r"(r[2]), "=r"(r[3]) : "r"(addr));
}
__device__ __forceinline__ void ldmx4t(uint32_t r[4], uint32_t addr) {
    asm volatile("ldmatrix.sync.aligned.m8n8.x4.trans.shared.b16 {%0,%1,%2,%3}, [%4];"
                 : "=r"(r[0]), "=r"(r[1]), "=r"(r[2]), "=r"(r[3]) : "r"(addr));
}
__device__ __forceinline__ void mma_bf16(float* c, const uint32_t* a, uint32_t b0, uint32_t b1) {
    asm volatile(
        "mma.sync.aligned.m16n8k16.row.col.f32.bf16.bf16.f32 "
        "{%0,%1,%2,%3}, {%4,%5,%6,%7}, {%8,%9}, {%0,%1,%2,%3};"
        : "+f"(c[0]), "+f"(c[1]), "+f"(c[2]), "+f"(c[3])
        : "r"(a[0]), "r"(a[1]), "r"(a[2]), "r"(a[3]), "r"(b0), "r"(b1));
}
__device__ __forceinline__ uint32_t packbf(float x, float y) {
    __nv_bfloat162 p = __float22bfloat162_rn(make_float2(x, y));
    return *reinterpret_cast<uint32_t*>(&p);
}
__device__ __forceinline__ void cp16(uint32_t dst, const void* src) {
    asm volatile("cp.async.cg.shared.global [%0], [%1], 16;" :: "r"(dst), "l"(src));
}
__device__ __forceinline__ void cp_commit() { asm volatile("cp.async.commit_group;"); }
template <int N> __device__ __forceinline__ void cp_wait() {
    asm volatile("cp.async.wait_group %0;" :: "n"(N));
}

// Stage one full 64x256 bf16 tile via cp.async.
// 4 threads per row; each thread copies 8 x 16B chunks at col = (tid&3)*8 + 32*h
// -> all 32 chunks (256 cols) per row covered.
__device__ __forceinline__ void stage_cp(uint32_t dst, const __nv_bfloat16* __restrict__ src,
                                         int tid) {
    int row = tid >> 2, c0 = (tid & 3) * 8;
    #pragma unroll
    for (int h = 0; h < 8; h++) {
        int col = c0 + 32 * h;
        cp16(dst + (uint32_t)(row * KSTR + col) * 2, src + row * D + col);
    }
}

// ---------------------------------------------------------------------------
// Kernel 0: states fp32 -> bf16 copy
// ---------------------------------------------------------------------------
__global__ void cvt_kernel(const float* __restrict__ x) {
    int i = blockIdx.x * blockDim.x + threadIdx.x;
    float4 t = reinterpret_cast<const float4*>(x)[i];
    uint2 u;
    u.x = packbf(t.x, t.y);
    u.y = packbf(t.z, t.w);
    reinterpret_cast<uint2*>(g_x)[i] = u;
}

// ---------------------------------------------------------------------------
// Kernel 1: q = states @ Wq, k = states @ Wk   (bf16 mma, blockIdx.z selects)
// ---------------------------------------------------------------------------
__global__ void gemm_qk_kernel(const float* __restrict__ x,
                               const float* __restrict__ Wq,
                               const float* __restrict__ Wk) {
    extern __shared__ char smraw[];
    __nv_bfloat16* Xs = (__nv_bfloat16*)smraw;        // [64][KSTR]
    __nv_bfloat16* Wg = Xs + TILE;                    // [64][KSTR]: Wg[n][k] = W[k][ntile+n]

    const float* W = (blockIdx.z == 0) ? Wq : Wk;
    __nv_bfloat16* out = (blockIdx.z == 0) ? g_q : g_k;

    int mtile = blockIdx.y * BM;
    int ntile = blockIdx.x * BN;
    int tid = threadIdx.x, lane = tid & 31, w = tid >> 5;
    int wr = w >> 1, wc = w & 1, gid = lane >> 2, q = lane & 3;

    for (int v = tid; v < BM * (D / 4); v += TPB) {
        int m = v >> 6, c4 = v & 63;
        float4 t = reinterpret_cast<const float4*>(x + (mtile + m) * D)[c4];
        uint2 u;
        u.x = packbf(t.x, t.y);
        u.y = packbf(t.z, t.w);
        *reinterpret_cast<uint2*>(Xs + m * KSTR + c4 * 4) = u;
    }
    for (int v = tid; v < D * (BN / 4); v += TPB) {
        int kk = v >> 4, n4 = (v & 15) * 4;
        float4 t = *reinterpret_cast<const float4*>(W + kk * D + ntile + n4);
        Wg[(n4 + 0) * KSTR + kk] = __float2bfloat16(t.x);
        Wg[(n4 + 1) * KSTR + kk] = __float2bfloat16(t.y);
        Wg[(n4 + 2) * KSTR + kk] = __float2bfloat16(t.z);
        Wg[(n4 + 3) * KSTR + kk] = __float2bfloat16(t.w);
    }
    __syncthreads();

    uint32_t xsa = smem_u32(Xs), wga = smem_u32(Wg);
    uint32_t qa_base = ((16 * wr + (lane & 15)) * KSTR + 8 * (lane >> 4)) * 2;
    uint32_t kb_base = ((32 * wc + (lane & 7) + 8 * (lane >> 4)) * KSTR + 8 * ((lane >> 3) & 1)) * 2;

    float c[4][4] = {};
    #pragma unroll
    for (int ks = 0; ks < 16; ks++) {
        uint32_t a[4], b0[4], b1[4];
        ldmx4(a, xsa + qa_base + ks * 32);
        ldmx4(b0, wga + kb_base + ks * 32);
        ldmx4(b1, wga + kb_base + 16 * KSTR * 2 + ks * 32);
        mma_bf16(c[0], a, b0[0], b0[1]);
        mma_bf16(c[1], a, b0[2], b0[3]);
        mma_bf16(c[2], a, b1[0], b1[1]);
        mma_bf16(c[3], a, b1[2], b1[3]);
    }

    int r0 = mtile + 16 * wr + gid;
    #pragma unroll
    for (int f = 0; f < 4; f++) {
        int col = ntile + 32 * wc + 8 * f + 2 * q;
        *reinterpret_cast<uint32_t*>(out + r0 * D + col)       = packbf(c[f][0], c[f][1]);
        *reinterpret_cast<uint32_t*>(out + (r0 + 8) * D + col) = packbf(c[f][2], c[f][3]);
    }
}

// ---------------------------------------------------------------------------
// Kernel 2: flash attention, software-pipelined:
//   stage1(jt) computes E(jt) into Es[jt&1]; stage2(jt-1) consumes Es[(jt-1)&1]
//   and Xs[(jt-1)%3] concurrently -> no intra-iteration E write->read sync.
// K/X staged by cp.async (Ks x2, Xs x3 since stage2 lags one tile).
// ---------------------------------------------------------------------------
__global__ void __launch_bounds__(TPB, 1) flash_attn_kernel() {
    extern __shared__ char smraw[];
    __nv_bfloat16* SM = (__nv_bfloat16*)smraw;
    __nv_bfloat16* Qs = SM;                               // [64][KSTR]
    uint32_t base = smem_u32(SM);
    uint32_t ksa[2] = {base + (uint32_t)(1 * TILE) * 2, base + (uint32_t)(2 * TILE) * 2};
    uint32_t xsa[3] = {base + (uint32_t)(3 * TILE) * 2, base + (uint32_t)(4 * TILE) * 2,
                       base + (uint32_t)(5 * TILE) * 2};
    __nv_bfloat16* Es0 = SM + 6 * TILE;                   // [64][ESTR] x2
    __nv_bfloat16* Es1 = Es0 + BM * ESTR;
    float* red = (float*)(Es1 + BM * ESTR);               // [2][64]

    int tid = threadIdx.x, lane = tid & 31, w = tid >> 5;
    int wr = w >> 1, wc = w & 1, gid = lane >> 2, q = lane & 3;
    int mtile = blockIdx.x * BM;

    // Stage resident Q tile
    const uint4* gq4 = reinterpret_cast<const uint4*>(g_q);
    #pragma unroll
    for (int i = 0; i < 8; i++) {
        uint4 t = gq4[(mtile + w + 8 * i) * 32 + lane];
        *((uint4*)(Qs + (w + 8 * i) * KSTR) + lane) = t;
    }
    // Prologue: tile-0 K/X via cp.async (group 0) — FULL tile coverage
    stage_cp(ksa[0], g_k, tid);
    stage_cp(xsa[0], g_x, tid);
    cp_commit();
    __syncthreads();   // Qs staged

    // Q fragments resident
    uint32_t qa = base + ((16 * wr + (lane & 15)) * KSTR + 8 * (lane >> 4)) * 2;
    uint32_t qfrag[16][4];
    #pragma unroll
    for (int ks = 0; ks < 16; ks++) ldmx4(qfrag[ks], qa + ks * 32);

    uint32_t kb_off = ((32 * wc + (lane & 7) + 8 * (lane >> 4)) * KSTR + 8 * ((lane >> 3) & 1)) * 2;
    uint32_t ea_base = ((16 * wr + (lane & 15)) * ESTR + 8 * (lane >> 4)) * 2;
    uint32_t xb_off = ((lane & 15) * KSTR + 8 * (lane >> 4)) * 2;
    uint32_t esa[2] = {smem_u32(Es0), smem_u32(Es1)};

    float acc[16][4];
    #pragma unroll
    for (int f = 0; f < 16; f++)
        acc[f][0] = acc[f][1] = acc[f][2] = acc[f][3] = 0.f;
    float den0 = 0.f, den1 = 0.f;

    for (int jt = 0; jt <= NT; jt++) {
        __syncthreads();   // sync A: prior readers of buffers about to be overwritten
        if (jt < NT) {
            if (jt + 1 < NT) {
                int jb = (jt + 1) * BN;
                stage_cp(ksa[(jt + 1) & 1], g_k + jb * D, tid);
                stage_cp(xsa[(jt + 1) % 3], g_x + jb * D, tid);
                cp_commit();
                cp_wait<1>();
            } else {
                cp_wait<0>();
            }
        }
        __syncthreads();   // sync B: staged tile + last iter's Es visible

        if (jt < NT) {
            // Stage 1: S = Q @ K^T on Ks[jt&1]
            float cS[4][4] = {};
            uint32_t kb = ksa[jt & 1] + kb_off;
            #pragma unroll
            for (int ks = 0; ks < 16; ks++) {
                uint32_t b0[4], b1[4];
                ldmx4(b0, kb + ks * 32);
                ldmx4(b1, kb + 16 * KSTR * 2 + ks * 32);
                mma_bf16(cS[0], qfrag[ks], b0[0], b0[1]);
                mma_bf16(cS[1], qfrag[ks], b0[2], b0[3]);
                mma_bf16(cS[2], qfrag[ks], b1[0], b1[1]);
                mma_bf16(cS[3], qfrag[ks], b1[2], b1[3]);
            }
            // E = exp(S/16) -> Es[jt&1]
            __nv_bfloat16* Ew = (jt & 1) ? Es1 : Es0;
            #pragma unroll
            for (int f = 0; f < 4; f++) {
                float e0 = __expf(cS[f][0] * 0.0625f);
                float e1 = __expf(cS[f][1] * 0.0625f);
                float e2 = __expf(cS[f][2] * 0.0625f);
                float e3 = __expf(cS[f][3] * 0.0625f);
                den0 += e0 + e1; den1 += e2 + e3;
                int col = 32 * wc + 8 * f + 2 * q;
                *reinterpret_cast<uint32_t*>(Ew + (16 * wr + gid) * ESTR + col)     = packbf(e0, e1);
                *reinterpret_cast<uint32_t*>(Ew + (16 * wr + gid + 8) * ESTR + col) = packbf(e2, e3);
            }
        }
        if (jt > 0) {
            // Stage 2: acc += E(jt-1) @ X(jt-1)
            int pj = jt - 1;
            uint32_t ea = esa[pj & 1] + ea_base;
            uint32_t xb = xsa[pj % 3] + xb_off;
            #pragma unroll
            for (int ks = 0; ks < 4; ks++) {
                uint32_t a[4];
                ldmx4(a, ea + ks * 32);
                #pragma unroll
                for (int u = 0; u < 8; u++) {
                    uint32_t b[4];
                    ldmx4t(b, xb + ks * (16 * KSTR * 2) + (128 * wc + 16 * u) * 2);
                    mma_bf16(acc[2 * u],     a, b[0], b[1]);
                    mma_bf16(acc[2 * u + 1], a, b[2], b[3]);
                }
            }
        }
    }

    // den reduce: quad lanes then cross-wc via smem
    den0 += __shfl_xor_sync(0xffffffffu, den0, 1);
    den0 += __shfl_xor_sync(0xffffffffu, den0, 2);
    den1 += __shfl_xor_sync(0xffffffffu, den1, 1);
    den1 += __shfl_xor_sync(0xffffffffu, den1, 2);
    __syncthreads();
    if (q == 0) {
        red[wc * 64 + 16 * wr + gid]     = den0;
        red[wc * 64 + 16 * wr + gid + 8] = den1;
    }
    __syncthreads();
    float rinv0 = 1.0f / (red[16 * wr + gid]     + red[64 + 16 * wr + gid]);
    float rinv1 = 1.0f / (red[16 * wr + gid + 8] + red[64 + 16 * wr + gid + 8]);

    float sq0 = 0.f, sq1 = 0.f;
    int r0 = mtile + 16 * wr + gid;
    #pragma unroll
    for (int f = 0; f < 16; f++) {
        int col = 128 * wc + 8 * f + 2 * q;
        uint32_t p0 = packbf(acc[f][0] * rinv0, acc[f][1] * rinv0);
        uint32_t p1 = packbf(acc[f][2] * rinv1, acc[f][3] * rinv1);
        *reinterpret_cast<uint32_t*>(g_attn + r0 * D + col)       = p0;
        *reinterpret_cast<uint32_t*>(g_attn + (r0 + 8) * D + col) = p1;
        float2 v0 = __bfloat1622float2(*reinterpret_cast<__nv_bfloat162*>(&p0));
        float2 v1 = __bfloat1622float2(*reinterpret_cast<__nv_bfloat162*>(&p1));
        sq0 += v0.x * v0.x + v0.y * v0.y;
        sq1 += v1.x * v1.x + v1.y * v1.y;
    }
    sq0 += __shfl_xor_sync(0xffffffffu, sq0, 1);
    sq0 += __shfl_xor_sync(0xffffffffu, sq0, 2);
    sq1 += __shfl_xor_sync(0xffffffffu, sq1, 1);
    sq1 += __shfl_xor_sync(0xffffffffu, sq1, 2);
    __syncthreads();
    if (q == 0) {
        red[wc * 64 + 16 * wr + gid]     = sq0;
        red[wc * 64 + 16 * wr + gid + 8] = sq1;
    }
    __syncthreads();
    if (tid < 64) g_sq[mtile + tid] = red[tid] + red[64 + tid];
}

// ---------------------------------------------------------------------------
// Kernel 3: RBF stage. A operand register-resident; B tiles + sqj double-
// buffered via cp.async (staging off the critical path).
// ---------------------------------------------------------------------------
__global__ void __launch_bounds__(TPB, 1) rbf_feat_kernel() {
    extern __shared__ char smraw[];
    __nv_bfloat16* As  = (__nv_bfloat16*)smraw;   // [64][KSTR] resident attn rows
    __nv_bfloat16* Bs0 = As + TILE;               // [64][KSTR] x2 (double buffer)
    __nv_bfloat16* Bs1 = Bs0 + TILE;
    float* sqjs = (float*)(Bs1 + TILE);           // [2][64]
    float* red  = sqjs + 128;                     // [4][64]

    int tid = threadIdx.x, lane = tid & 31, w = tid >> 5;
    int wr = w >> 2, wc = w & 3, gid = lane >> 2, q = lane & 3;
    int mtile = blockIdx.x * BM;

    uint32_t bsa[2] = {smem_u32(Bs0), smem_u32(Bs1)};
    uint32_t sqa = smem_u32(sqjs);

    const uint4* ga4 = reinterpret_cast<const uint4*>(g_attn);
    #pragma unroll
    for (int i = 0; i < 8; i++) {
        uint4 t = ga4[(mtile + w + 8 * i) * 32 + lane];
        *((uint4*)(As + (w + 8 * i) * KSTR) + lane) = t;
    }
    // Prologue: tile-0 B + sqj via cp.async (group 0) — FULL tile coverage
    stage_cp(bsa[0], g_attn, tid);
    if (tid < 16) cp16(sqa + tid * 16, g_sq + tid * 4);
    cp_commit();
    __syncthreads();   // As staged

    // A fragments resident: rows 32*wr + {0..31}, all K (128 regs)
    uint32_t aa0 = smem_u32(As) + ((32 * wr + (lane & 15)) * KSTR + 8 * (lane >> 4)) * 2;
    uint32_t afrag[16][2][4];
    #pragma unroll
    for (int ks = 0; ks < 16; ks++) {
        ldmx4(afrag[ks][0], aa0 + ks * 32);
        ldmx4(afrag[ks][1], aa0 + 16 * KSTR * 2 + ks * 32);
    }

    uint32_t kb_off = ((16 * wc + (lane & 7) + 8 * (lane >> 4)) * KSTR + 8 * ((lane >> 3) & 1)) * 2;

    float sqi[2][2], fs[2][2] = {};
    #pragma unroll
    for (int g = 0; g < 2; g++) {
        sqi[g][0] = g_sq[mtile + 32 * wr + 16 * g + gid];
        sqi[g][1] = g_sq[mtile + 32 * wr + 16 * g + gid + 8];
    }

    for (int jt = 0; jt < NT; jt++) {
        int cur = jt & 1;
        if (jt + 1 < NT) {
            int jb = (jt + 1) * BN;
            stage_cp(bsa[1 - cur], g_attn + jb * D, tid);
            if (tid < 16) cp16(sqa + (1 - cur) * 256 + tid * 16, g_sq + jb + tid * 4);
            cp_commit();
            cp_wait<1>();
        } else {
            cp_wait<0>();
        }
        __syncthreads();   // Bs[cur]/sqjs[cur] visible

        float cf[2][2][4] = {};
        uint32_t kb = bsa[cur] + kb_off;
        #pragma unroll
        for (int ks = 0; ks < 16; ks++) {
            uint32_t b[4];
            ldmx4(b, kb + ks * 32);
            mma_bf16(cf[0][0], afrag[ks][0], b[0], b[1]);
            mma_bf16(cf[0][1], afrag[ks][0], b[2], b[3]);
            mma_bf16(cf[1][0], afrag[ks][1], b[0], b[1]);
            mma_bf16(cf[1][1], afrag[ks][1], b[2], b[3]);
        }

        const float* sqj = sqjs + cur * 64;
        #pragma unroll
        for (int g = 0; g < 2; g++) {
            #pragma unroll
            for (int c = 0; c < 2; c++) {
                int col = 16 * wc + 8 * c + 2 * q;
                float sj0 = sqj[col], sj1 = sqj[col + 1];
                fs[g][0] += __expf(-fmaxf(sqi[g][0] + sj0 - 2.0f * cf[g][c][0], 0.0f));
                fs[g][0] += __expf(-fmaxf(sqi[g][0] + sj1 - 2.0f * cf[g][c][1], 0.0f));
                fs[g][1] += __expf(-fmaxf(sqi[g][1] + sj0 - 2.0f * cf[g][c][2], 0.0f));
                fs[g][1] += __expf(-fmaxf(sqi[g][1] + sj1 - 2.0f * cf[g][c][3], 0.0f));
            }
        }
        __syncthreads();   // readers done before next iteration overwrites Bs[cur]
    }

    #pragma unroll
    for (int g = 0; g < 2; g++) {
        #pragma unroll
        for (int h = 0; h < 2; h++) {
            fs[g][h] += __shfl_xor_sync(0xffffffffu, fs[g][h], 1);
            fs[g][h] += __shfl_xor_sync(0xffffffffu, fs[g][h], 2);
        }
    }
    if (q == 0) {
        #pragma unroll
        for (int g = 0; g < 2; g++) {
            red[wc * 64 + 32 * wr + 16 * g + gid]     = fs[g][0];
            red[wc * 64 + 32 * wr + 16 * g + gid + 8] = fs[g][1];
        }
    }
    __syncthreads();
    if (tid < 64)
        g_feat[mtile + tid] = (red[tid] + red[64 + tid] + red[128 + tid] + red[192 + tid])
                              * (1.0f / (float)N_TOK);
}

// ---------------------------------------------------------------------------
// Kernel 4: MLP head
// ---------------------------------------------------------------------------
__global__ void mlp_kernel(const float* __restrict__ W1, const float* __restrict__ b1,
                           const float* __restrict__ W2, const float* __restrict__ b2,
                           float* __restrict__ out) {
    __shared__ float w1[64], bb1[64], w2[64];
    int tid = threadIdx.x;
    if (tid < 64) { w1[tid] = W1[tid]; bb1[tid] = b1[tid]; w2[tid] = W2[tid]; }
    __syncthreads();
    int i = blockIdx.x * blockDim.x + tid;
    if (i >= N_TOK) return;
    float f = g_feat[i];
    float a = b2[0];
    #pragma unroll
    for (int k2 = 0; k2 < 64; k2++) {
        float h = fmaf(f, w1[k2], bb1[k2]);
        a = fmaf(fmaxf(h, 0.0f), w2[k2], a);
    }
    out[i] = a;
}

// ---------------------------------------------------------------------------
extern "C" void kernel_launch(void* const* d_in, const int* in_sizes, int n_in,
                              void* d_out, int out_size) {
    const float* states = (const float*)d_in[0];
    const float* Wq     = (const float*)d_in[1];
    const float* Wk     = (const float*)d_in[2];
    const float* W1     = (const float*)d_in[3];
    const float* b1     = (const float*)d_in[4];
    const float* W2     = (const float*)d_in[5];
    const float* b2     = (const float*)d_in[6];
    float* out = (float*)d_out;
    (void)in_sizes; (void)n_in; (void)out_size;

    size_t smem_qk    = (size_t)(2 * TILE) * 2;
    size_t smem_flash = (size_t)(6 * TILE + 2 * BM * ESTR) * 2 + 512;
    size_t smem_rbf   = (size_t)(3 * TILE) * 2 + (128 + 256) * 4;

    (void)cudaFuncSetAttribute(gemm_qk_kernel,    cudaFuncAttributeMaxDynamicSharedMemorySize, (int)smem_qk);
    (void)cudaFuncSetAttribute(flash_attn_kernel, cudaFuncAttributeMaxDynamicSharedMemorySize, (int)smem_flash);
    (void)cudaFuncSetAttribute(rbf_feat_kernel,   cudaFuncAttributeMaxDynamicSharedMemorySize, (int)smem_rbf);

    cvt_kernel<<<(N_TOK * D / 4) / TPB, TPB>>>(states);
    dim3 g1(D / BN, N_TOK / BM, 2);
    gemm_qk_kernel<<<g1, TPB, smem_qk>>>(states, Wq, Wk);
    flash_attn_kernel<<<N_TOK / BM, TPB, smem_flash>>>();
    rbf_feat_kernel<<<N_TOK / BM, TPB, smem_rbf>>>();
    mlp_kernel<<<N_TOK / TPB, TPB>>>(W1, b1, W2, b2, out);
}

// round 11
// speedup vs baseline: 1.1023x; 1.1023x over previous
#include <cuda_runtime.h>
#include <cuda_bf16.h>
#include <math.h>
#include <stdint.h>

#define N_TOK 8192
#define D 256
#define BM 64
#define BN 64
#define TPB 256
#define KSTR 264   // bf16 stride for [64][256] tiles: 528B rows, ldmatrix conflict-free
#define ESTR 72    // bf16 stride for E tile [64][64]
#define NT (N_TOK / BN)
#define TILE (BM * KSTR)   // elements per staged tile

// flash smem: Qs + 2*Ks + 3*Xs + 2*Es + red
static_assert((6 * TILE + 2 * BM * ESTR) * 2 + 512 <= 232448, "flash smem");

__device__ __align__(16) __nv_bfloat16 g_q[N_TOK * D];
__device__ __align__(16) __nv_bfloat16 g_k[N_TOK * D];
__device__ __align__(16) __nv_bfloat16 g_x[N_TOK * D];
__device__ __align__(16) __nv_bfloat16 g_attn[N_TOK * D];
__device__ float g_sq[N_TOK];
__device__ float g_feat[N_TOK];

__device__ __forceinline__ uint32_t smem_u32(const void* p) {
    return (uint32_t)__cvta_generic_to_shared(p);
}
__device__ __forceinline__ void ldmx4(uint32_t r[4], uint32_t addr) {
    asm volatile("ldmatrix.sync.aligned.m8n8.x4.shared.b16 {%0,%1,%2,%3}, [%4];"
                 : "=r"(r[0]), "=r"(r[1]), "=r"(r[2]), "=r"(r[3]) : "r"(addr));
}
__device__ __forceinline__ void ldmx4t(uint32_t r[4], uint32_t addr) {
    asm volatile("ldmatrix.sync.aligned.m8n8.x4.trans.shared.b16 {%0,%1,%2,%3}, [%4];"
                 : "=r"(r[0]), "=r"(r[1]), "=r"(r[2]), "=r"(r[3]) : "r"(addr));
}
__device__ __forceinline__ void mma_bf16(float* c, const uint32_t* a, uint32_t b0, uint32_t b1) {
    asm volatile(
        "mma.sync.aligned.m16n8k16.row.col.f32.bf16.bf16.f32 "
        "{%0,%1,%2,%3}, {%4,%5,%6,%7}, {%8,%9}, {%0,%1,%2,%3};"
        : "+f"(c[0]), "+f"(c[1]), "+f"(c[2]), "+f"(c[3])
        : "r"(a[0]), "r"(a[1]), "r"(a[2]), "r"(a[3]), "r"(b0), "r"(b1));
}
__device__ __forceinline__ uint32_t packbf(float x, float y) {
    __nv_bfloat162 p = __float22bfloat162_rn(make_float2(x, y));
    return *reinterpret_cast<uint32_t*>(&p);
}
__device__ __forceinline__ void cp16(uint32_t dst, const void* src) {
    asm volatile("cp.async.cg.shared.global [%0], [%1], 16;" :: "r"(dst), "l"(src));
}
__device__ __forceinline__ void cp_commit() { asm volatile("cp.async.commit_group;"); }
template <int N> __device__ __forceinline__ void cp_wait() {
    asm volatile("cp.async.wait_group %0;" :: "n"(N));
}

// Stage one full 64x256 bf16 tile via cp.async — ROW-PER-WARP mapping.
// Warp w stages rows 8w..8w+7; per LDGSTS instruction a warp covers ONE row:
// 32 lanes x 16B = 512B contiguous global read (fully coalesced), and smem
// store banks 4*(row+l)+0..3 -> conflict-free (this mapping is the R10 fix:
// the old row-interleaved mapping had a 4-way store-bank conflict per op).
__device__ __forceinline__ void stage_cp(uint32_t dst, const __nv_bfloat16* __restrict__ src,
                                         int tid) {
    int w = tid >> 5, lane = tid & 31;
    #pragma unroll
    for (int h = 0; h < 8; h++) {
        int row = w * 8 + h;
        cp16(dst + (uint32_t)(row * KSTR + lane * 8) * 2, src + row * D + lane * 8);
    }
}

// ---------------------------------------------------------------------------
// Kernel 0: states fp32 -> bf16 copy
// ---------------------------------------------------------------------------
__global__ void cvt_kernel(const float* __restrict__ x) {
    int i = blockIdx.x * blockDim.x + threadIdx.x;
    float4 t = reinterpret_cast<const float4*>(x)[i];
    uint2 u;
    u.x = packbf(t.x, t.y);
    u.y = packbf(t.z, t.w);
    reinterpret_cast<uint2*>(g_x)[i] = u;
}

// ---------------------------------------------------------------------------
// Kernel 1: q = states @ Wq, k = states @ Wk   (bf16 mma, blockIdx.z selects)
// ---------------------------------------------------------------------------
__global__ void gemm_qk_kernel(const float* __restrict__ x,
                               const float* __restrict__ Wq,
                               const float* __restrict__ Wk) {
    extern __shared__ char smraw[];
    __nv_bfloat16* Xs = (__nv_bfloat16*)smraw;        // [64][KSTR]
    __nv_bfloat16* Wg = Xs + TILE;                    // [64][KSTR]: Wg[n][k] = W[k][ntile+n]

    const float* W = (blockIdx.z == 0) ? Wq : Wk;
    __nv_bfloat16* out = (blockIdx.z == 0) ? g_q : g_k;

    int mtile = blockIdx.y * BM;
    int ntile = blockIdx.x * BN;
    int tid = threadIdx.x, lane = tid & 31, w = tid >> 5;
    int wr = w >> 1, wc = w & 1, gid = lane >> 2, q = lane & 3;

    for (int v = tid; v < BM * (D / 4); v += TPB) {
        int m = v >> 6, c4 = v & 63;
        float4 t = reinterpret_cast<const float4*>(x + (mtile + m) * D)[c4];
        uint2 u;
        u.x = packbf(t.x, t.y);
        u.y = packbf(t.z, t.w);
        *reinterpret_cast<uint2*>(Xs + m * KSTR + c4 * 4) = u;
    }
    for (int v = tid; v < D * (BN / 4); v += TPB) {
        int kk = v >> 4, n4 = (v & 15) * 4;
        float4 t = *reinterpret_cast<const float4*>(W + kk * D + ntile + n4);
        Wg[(n4 + 0) * KSTR + kk] = __float2bfloat16(t.x);
        Wg[(n4 + 1) * KSTR + kk] = __float2bfloat16(t.y);
        Wg[(n4 + 2) * KSTR + kk] = __float2bfloat16(t.z);
        Wg[(n4 + 3) * KSTR + kk] = __float2bfloat16(t.w);
    }
    __syncthreads();

    uint32_t xsa = smem_u32(Xs), wga = smem_u32(Wg);
    uint32_t qa_base = ((16 * wr + (lane & 15)) * KSTR + 8 * (lane >> 4)) * 2;
    uint32_t kb_base = ((32 * wc + (lane & 7) + 8 * (lane >> 4)) * KSTR + 8 * ((lane >> 3) & 1)) * 2;

    float c[4][4] = {};
    #pragma unroll
    for (int ks = 0; ks < 16; ks++) {
        uint32_t a[4], b0[4], b1[4];
        ldmx4(a, xsa + qa_base + ks * 32);
        ldmx4(b0, wga + kb_base + ks * 32);
        ldmx4(b1, wga + kb_base + 16 * KSTR * 2 + ks * 32);
        mma_bf16(c[0], a, b0[0], b0[1]);
        mma_bf16(c[1], a, b0[2], b0[3]);
        mma_bf16(c[2], a, b1[0], b1[1]);
        mma_bf16(c[3], a, b1[2], b1[3]);
    }

    int r0 = mtile + 16 * wr + gid;
    #pragma unroll
    for (int f = 0; f < 4; f++) {
        int col = ntile + 32 * wc + 8 * f + 2 * q;
        *reinterpret_cast<uint32_t*>(out + r0 * D + col)       = packbf(c[f][0], c[f][1]);
        *reinterpret_cast<uint32_t*>(out + (r0 + 8) * D + col) = packbf(c[f][2], c[f][3]);
    }
}

// ---------------------------------------------------------------------------
// Kernel 2: flash attention, software-pipelined:
//   stage1(jt) computes E(jt) into Es[jt&1]; stage2(jt-1) consumes Es[(jt-1)&1]
//   and Xs[(jt-1)%3] concurrently -> no intra-iteration E write->read sync.
// K/X staged by cp.async (Ks x2, Xs x3 since stage2 lags one tile).
// ---------------------------------------------------------------------------
__global__ void __launch_bounds__(TPB, 1) flash_attn_kernel() {
    extern __shared__ char smraw[];
    __nv_bfloat16* SM = (__nv_bfloat16*)smraw;
    __nv_bfloat16* Qs = SM;                               // [64][KSTR]
    uint32_t base = smem_u32(SM);
    uint32_t ksa[2] = {base + (uint32_t)(1 * TILE) * 2, base + (uint32_t)(2 * TILE) * 2};
    uint32_t xsa[3] = {base + (uint32_t)(3 * TILE) * 2, base + (uint32_t)(4 * TILE) * 2,
                       base + (uint32_t)(5 * TILE) * 2};
    __nv_bfloat16* Es0 = SM + 6 * TILE;                   // [64][ESTR] x2
    __nv_bfloat16* Es1 = Es0 + BM * ESTR;
    float* red = (float*)(Es1 + BM * ESTR);               // [2][64]

    int tid = threadIdx.x, lane = tid & 31, w = tid >> 5;
    int wr = w >> 1, wc = w & 1, gid = lane >> 2, q = lane & 3;
    int mtile = blockIdx.x * BM;

    // Stage resident Q tile
    const uint4* gq4 = reinterpret_cast<const uint4*>(g_q);
    #pragma unroll
    for (int i = 0; i < 8; i++) {
        uint4 t = gq4[(mtile + w + 8 * i) * 32 + lane];
        *((uint4*)(Qs + (w + 8 * i) * KSTR) + lane) = t;
    }
    // Prologue: tile-0 K/X via cp.async (group 0)
    stage_cp(ksa[0], g_k, tid);
    stage_cp(xsa[0], g_x, tid);
    cp_commit();
    __syncthreads();   // Qs staged

    // Q fragments resident
    uint32_t qa = base + ((16 * wr + (lane & 15)) * KSTR + 8 * (lane >> 4)) * 2;
    uint32_t qfrag[16][4];
    #pragma unroll
    for (int ks = 0; ks < 16; ks++) ldmx4(qfrag[ks], qa + ks * 32);

    uint32_t kb_off = ((32 * wc + (lane & 7) + 8 * (lane >> 4)) * KSTR + 8 * ((lane >> 3) & 1)) * 2;
    uint32_t ea_base = ((16 * wr + (lane & 15)) * ESTR + 8 * (lane >> 4)) * 2;
    uint32_t xb_off = ((lane & 15) * KSTR + 8 * (lane >> 4)) * 2;
    uint32_t esa[2] = {smem_u32(Es0), smem_u32(Es1)};

    float acc[16][4];
    #pragma unroll
    for (int f = 0; f < 16; f++)
        acc[f][0] = acc[f][1] = acc[f][2] = acc[f][3] = 0.f;
    float den0 = 0.f, den1 = 0.f;

    for (int jt = 0; jt <= NT; jt++) {
        __syncthreads();   // sync A: prior readers of buffers about to be overwritten
        if (jt < NT) {
            if (jt + 1 < NT) {
                int jb = (jt + 1) * BN;
                stage_cp(ksa[(jt + 1) & 1], g_k + jb * D, tid);
                stage_cp(xsa[(jt + 1) % 3], g_x + jb * D, tid);
                cp_commit();
                cp_wait<1>();
            } else {
                cp_wait<0>();
            }
        }
        __syncthreads();   // sync B: staged tile + last iter's Es visible

        if (jt < NT) {
            // Stage 1: S = Q @ K^T on Ks[jt&1]
            float cS[4][4] = {};
            uint32_t kb = ksa[jt & 1] + kb_off;
            #pragma unroll
            for (int ks = 0; ks < 16; ks++) {
                uint32_t b0[4], b1[4];
                ldmx4(b0, kb + ks * 32);
                ldmx4(b1, kb + 16 * KSTR * 2 + ks * 32);
                mma_bf16(cS[0], qfrag[ks], b0[0], b0[1]);
                mma_bf16(cS[1], qfrag[ks], b0[2], b0[3]);
                mma_bf16(cS[2], qfrag[ks], b1[0], b1[1]);
                mma_bf16(cS[3], qfrag[ks], b1[2], b1[3]);
            }
            // E = exp(S/16) -> Es[jt&1]
            __nv_bfloat16* Ew = (jt & 1) ? Es1 : Es0;
            #pragma unroll
            for (int f = 0; f < 4; f++) {
                float e0 = __expf(cS[f][0] * 0.0625f);
                float e1 = __expf(cS[f][1] * 0.0625f);
                float e2 = __expf(cS[f][2] * 0.0625f);
                float e3 = __expf(cS[f][3] * 0.0625f);
                den0 += e0 + e1; den1 += e2 + e3;
                int col = 32 * wc + 8 * f + 2 * q;
                *reinterpret_cast<uint32_t*>(Ew + (16 * wr + gid) * ESTR + col)     = packbf(e0, e1);
                *reinterpret_cast<uint32_t*>(Ew + (16 * wr + gid + 8) * ESTR + col) = packbf(e2, e3);
            }
        }
        if (jt > 0) {
            // Stage 2: acc += E(jt-1) @ X(jt-1)
            int pj = jt - 1;
            uint32_t ea = esa[pj & 1] + ea_base;
            uint32_t xb = xsa[pj % 3] + xb_off;
            #pragma unroll
            for (int ks = 0; ks < 4; ks++) {
                uint32_t a[4];
                ldmx4(a, ea + ks * 32);
                #pragma unroll
                for (int u = 0; u < 8; u++) {
                    uint32_t b[4];
                    ldmx4t(b, xb + ks * (16 * KSTR * 2) + (128 * wc + 16 * u) * 2);
                    mma_bf16(acc[2 * u],     a, b[0], b[1]);
                    mma_bf16(acc[2 * u + 1], a, b[2], b[3]);
                }
            }
        }
    }

    // den reduce: quad lanes then cross-wc via smem
    den0 += __shfl_xor_sync(0xffffffffu, den0, 1);
    den0 += __shfl_xor_sync(0xffffffffu, den0, 2);
    den1 += __shfl_xor_sync(0xffffffffu, den1, 1);
    den1 += __shfl_xor_sync(0xffffffffu, den1, 2);
    __syncthreads();
    if (q == 0) {
        red[wc * 64 + 16 * wr + gid]     = den0;
        red[wc * 64 + 16 * wr + gid + 8] = den1;
    }
    __syncthreads();
    float rinv0 = 1.0f / (red[16 * wr + gid]     + red[64 + 16 * wr + gid]);
    float rinv1 = 1.0f / (red[16 * wr + gid + 8] + red[64 + 16 * wr + gid + 8]);

    float sq0 = 0.f, sq1 = 0.f;
    int r0 = mtile + 16 * wr + gid;
    #pragma unroll
    for (int f = 0; f < 16; f++) {
        int col = 128 * wc + 8 * f + 2 * q;
        uint32_t p0 = packbf(acc[f][0] * rinv0, acc[f][1] * rinv0);
        uint32_t p1 = packbf(acc[f][2] * rinv1, acc[f][3] * rinv1);
        *reinterpret_cast<uint32_t*>(g_attn + r0 * D + col)       = p0;
        *reinterpret_cast<uint32_t*>(g_attn + (r0 + 8) * D + col) = p1;
        float2 v0 = __bfloat1622float2(*reinterpret_cast<__nv_bfloat162*>(&p0));
        float2 v1 = __bfloat1622float2(*reinterpret_cast<__nv_bfloat162*>(&p1));
        sq0 += v0.x * v0.x + v0.y * v0.y;
        sq1 += v1.x * v1.x + v1.y * v1.y;
    }
    sq0 += __shfl_xor_sync(0xffffffffu, sq0, 1);
    sq0 += __shfl_xor_sync(0xffffffffu, sq0, 2);
    sq1 += __shfl_xor_sync(0xffffffffu, sq1, 1);
    sq1 += __shfl_xor_sync(0xffffffffu, sq1, 2);
    __syncthreads();
    if (q == 0) {
        red[wc * 64 + 16 * wr + gid]     = sq0;
        red[wc * 64 + 16 * wr + gid + 8] = sq1;
    }
    __syncthreads();
    if (tid < 64) g_sq[mtile + tid] = red[tid] + red[64 + tid];
}

// ---------------------------------------------------------------------------
// Kernel 3: RBF stage. A operand register-resident; B tiles + sqj double-
// buffered via cp.async (conflict-free staging, off the critical path).
// ---------------------------------------------------------------------------
__global__ void __launch_bounds__(TPB, 1) rbf_feat_kernel() {
    extern __shared__ char smraw[];
    __nv_bfloat16* As  = (__nv_bfloat16*)smraw;   // [64][KSTR] resident attn rows
    __nv_bfloat16* Bs0 = As + TILE;               // [64][KSTR] x2 (double buffer)
    __nv_bfloat16* Bs1 = Bs0 + TILE;
    float* sqjs = (float*)(Bs1 + TILE);           // [2][64]
    float* red  = sqjs + 128;                     // [4][64]

    int tid = threadIdx.x, lane = tid & 31, w = tid >> 5;
    int wr = w >> 2, wc = w & 3, gid = lane >> 2, q = lane & 3;
    int mtile = blockIdx.x * BM;

    uint32_t bsa[2] = {smem_u32(Bs0), smem_u32(Bs1)};
    uint32_t sqa = smem_u32(sqjs);

    const uint4* ga4 = reinterpret_cast<const uint4*>(g_attn);
    #pragma unroll
    for (int i = 0; i < 8; i++) {
        uint4 t = ga4[(mtile + w + 8 * i) * 32 + lane];
        *((uint4*)(As + (w + 8 * i) * KSTR) + lane) = t;
    }
    // Prologue: tile-0 B + sqj via cp.async (group 0)
    stage_cp(bsa[0], g_attn, tid);
    if (tid < 16) cp16(sqa + tid * 16, g_sq + tid * 4);
    cp_commit();
    __syncthreads();   // As staged

    // A fragments resident: rows 32*wr + {0..31}, all K (128 regs)
    uint32_t aa0 = smem_u32(As) + ((32 * wr + (lane & 15)) * KSTR + 8 * (lane >> 4)) * 2;
    uint32_t afrag[16][2][4];
    #pragma unroll
    for (int ks = 0; ks < 16; ks++) {
        ldmx4(afrag[ks][0], aa0 + ks * 32);
        ldmx4(afrag[ks][1], aa0 + 16 * KSTR * 2 + ks * 32);
    }

    uint32_t kb_off = ((16 * wc + (lane & 7) + 8 * (lane >> 4)) * KSTR + 8 * ((lane >> 3) & 1)) * 2;

    float sqi[2][2], fs[2][2] = {};
    #pragma unroll
    for (int g = 0; g < 2; g++) {
        sqi[g][0] = g_sq[mtile + 32 * wr + 16 * g + gid];
        sqi[g][1] = g_sq[mtile + 32 * wr + 16 * g + gid + 8];
    }

    for (int jt = 0; jt < NT; jt++) {
        int cur = jt & 1;
        if (jt + 1 < NT) {
            int jb = (jt + 1) * BN;
            stage_cp(bsa[1 - cur], g_attn + jb * D, tid);
            if (tid < 16) cp16(sqa + (1 - cur) * 256 + tid * 16, g_sq + jb + tid * 4);
            cp_commit();
            cp_wait<1>();
        } else {
            cp_wait<0>();
        }
        __syncthreads();   // Bs[cur]/sqjs[cur] visible

        float cf[2][2][4] = {};
        uint32_t kb = bsa[cur] + kb_off;
        #pragma unroll
        for (int ks = 0; ks < 16; ks++) {
            uint32_t b[4];
            ldmx4(b, kb + ks * 32);
            mma_bf16(cf[0][0], afrag[ks][0], b[0], b[1]);
            mma_bf16(cf[0][1], afrag[ks][0], b[2], b[3]);
            mma_bf16(cf[1][0], afrag[ks][1], b[0], b[1]);
            mma_bf16(cf[1][1], afrag[ks][1], b[2], b[3]);
        }

        const float* sqj = sqjs + cur * 64;
        #pragma unroll
        for (int g = 0; g < 2; g++) {
            #pragma unroll
            for (int c = 0; c < 2; c++) {
                int col = 16 * wc + 8 * c + 2 * q;
                float sj0 = sqj[col], sj1 = sqj[col + 1];
                fs[g][0] += __expf(-fmaxf(sqi[g][0] + sj0 - 2.0f * cf[g][c][0], 0.0f));
                fs[g][0] += __expf(-fmaxf(sqi[g][0] + sj1 - 2.0f * cf[g][c][1], 0.0f));
                fs[g][1] += __expf(-fmaxf(sqi[g][1] + sj0 - 2.0f * cf[g][c][2], 0.0f));
                fs[g][1] += __expf(-fmaxf(sqi[g][1] + sj1 - 2.0f * cf[g][c][3], 0.0f));
            }
        }
        __syncthreads();   // readers done before next iteration overwrites Bs[cur]
    }

    #pragma unroll
    for (int g = 0; g < 2; g++) {
        #pragma unroll
        for (int h = 0; h < 2; h++) {
            fs[g][h] += __shfl_xor_sync(0xffffffffu, fs[g][h], 1);
            fs[g][h] += __shfl_xor_sync(0xffffffffu, fs[g][h], 2);
        }
    }
    if (q == 0) {
        #pragma unroll
        for (int g = 0; g < 2; g++) {
            red[wc * 64 + 32 * wr + 16 * g + gid]     = fs[g][0];
            red[wc * 64 + 32 * wr + 16 * g + gid + 8] = fs[g][1];
        }
    }
    __syncthreads();
    if (tid < 64)
        g_feat[mtile + tid] = (red[tid] + red[64 + tid] + red[128 + tid] + red[192 + tid])
                              * (1.0f / (float)N_TOK);
}

// ---------------------------------------------------------------------------
// Kernel 4: MLP head
// ---------------------------------------------------------------------------
__global__ void mlp_kernel(const float* __restrict__ W1, const float* __restrict__ b1,
                           const float* __restrict__ W2, const float* __restrict__ b2,
                           float* __restrict__ out) {
    __shared__ float w1[64], bb1[64], w2[64];
    int tid = threadIdx.x;
    if (tid < 64) { w1[tid] = W1[tid]; bb1[tid] = b1[tid]; w2[tid] = W2[tid]; }
    __syncthreads();
    int i = blockIdx.x * blockDim.x + tid;
    if (i >= N_TOK) return;
    float f = g_feat[i];
    float a = b2[0];
    #pragma unroll
    for (int k2 = 0; k2 < 64; k2++) {
        float h = fmaf(f, w1[k2], bb1[k2]);
        a = fmaf(fmaxf(h, 0.0f), w2[k2], a);
    }
    out[i] = a;
}

// ---------------------------------------------------------------------------
extern "C" void kernel_launch(void* const* d_in, const int* in_sizes, int n_in,
                              void* d_out, int out_size) {
    const float* states = (const float*)d_in[0];
    const float* Wq     = (const float*)d_in[1];
    const float* Wk     = (const float*)d_in[2];
    const float* W1     = (const float*)d_in[3];
    const float* b1     = (const float*)d_in[4];
    const float* W2     = (const float*)d_in[5];
    const float* b2     = (const float*)d_in[6];
    float* out = (float*)d_out;
    (void)in_sizes; (void)n_in; (void)out_size;

    size_t smem_qk    = (size_t)(2 * TILE) * 2;
    size_t smem_flash = (size_t)(6 * TILE + 2 * BM * ESTR) * 2 + 512;
    size_t smem_rbf   = (size_t)(3 * TILE) * 2 + (128 + 256) * 4;

    (void)cudaFuncSetAttribute(gemm_qk_kernel,    cudaFuncAttributeMaxDynamicSharedMemorySize, (int)smem_qk);
    (void)cudaFuncSetAttribute(flash_attn_kernel, cudaFuncAttributeMaxDynamicSharedMemorySize, (int)smem_flash);
    (void)cudaFuncSetAttribute(rbf_feat_kernel,   cudaFuncAttributeMaxDynamicSharedMemorySize, (int)smem_rbf);

    cvt_kernel<<<(N_TOK * D / 4) / TPB, TPB>>>(states);
    dim3 g1(D / BN, N_TOK / BM, 2);
    gemm_qk_kernel<<<g1, TPB, smem_qk>>>(states, Wq, Wk);
    flash_attn_kernel<<<N_TOK / BM, TPB, smem_flash>>>();
    rbf_feat_kernel<<<N_TOK / BM, TPB, smem_rbf>>>();
    mlp_kernel<<<N_TOK / TPB, TPB>>>(W1, b1, W2, b2, out);
}